// round 12
// baseline (speedup 1.0000x reference)
#include <cuda_runtime.h>
#include <cuda_fp16.h>

// y = irfft2(rfft2(pad(u)) * rfft2(pad(k)), ortho) cropped.
// (4,64,251,509) fp32 -> 256 images 251x509, pad to 256x512.
// Pack z = u + i*k; with Z2 = FFT2(z):
//   P = U2*K2 = -0.25i*(Z2[ky,kx]^2 - conj(Z2[-ky,-kx])^2)
// conj(Z2[-ky,-kx]) = FFT_col(conj(Z[h,-kx])) -- conj-on-load, no gather.
// Combined ortho scale 2^-25.5 folded into the product.
// fp16 intermediates (tol 1e-3): g_Zh raw, g_Ph pre-scaled 2^6, T2 2^12.
// Stage2: 8-column tiles, 128-thread blocks (45KB smem -> 5 blocks/SM).
// Stage3 pairs two rows per inverse FFT-512 (y1 = Re, y2 = Im): exact.

#define IMGS 256
#define HH   251
#define WW   509
#define NJ   257
#define ZP   516   // half2 row stride of Z scratch
#define WPAD 260   // half2 row stride of product scratch
#define EX1S 10    // fft512 exchange-1 stride (16B aligned, conflict-free)
#define P512B 66   // fft512 exchange-2 stride (conflict-free both sides)
#define SROW 656   // smem float2 for fft512 (>= 64*10)
#define E2S  18    // fft256 exchange per-thread stride (float2)
#define E2C  288   // fft256 exchange per-column stride (float2) = 16*18
#define MST  9     // stage2 staging tile stride (half2)

__device__ __half2 g_Zh[IMGS * HH * ZP];   // packed row spectra (fp16)
__device__ __half2 g_Ph[IMGS * HH * WPAD]; // product half-spectrum (fp16, x64)
__device__ float2  g_tw[512];              // tw[r] = exp(-2*pi*i*r/512)

__global__ void init_tw_kernel() {
    int r = threadIdx.x;
    double ang = -2.0 * 3.141592653589793238462643383279502884 * (double)r / 512.0;
    g_tw[r] = make_float2((float)cos(ang), (float)sin(ang));
}

__device__ __forceinline__ float2 cmul(float2 a, float2 b) {
    return make_float2(a.x*b.x - a.y*b.y, a.x*b.y + a.y*b.x);
}
__device__ __forceinline__ float2 cadd(float2 a, float2 b) { return make_float2(a.x+b.x, a.y+b.y); }
__device__ __forceinline__ float2 csub(float2 a, float2 b) { return make_float2(a.x-b.x, a.y-b.y); }
template<int DIR>
__device__ __forceinline__ float2 mulmi(float2 v) {   // * (-i) fwd, * (+i) inv
    return (DIR == 1) ? make_float2(v.y, -v.x) : make_float2(-v.y, v.x);
}

template<int DIR>
__device__ __forceinline__ void dft8(float2 x[8]) {
    const float C = 0.70710678118654752f;
    float2 t0 = cadd(x[0], x[4]), t4 = csub(x[0], x[4]);
    float2 t1 = cadd(x[1], x[5]), t5 = csub(x[1], x[5]);
    float2 t2 = cadd(x[2], x[6]), t6 = csub(x[2], x[6]);
    float2 t3 = cadd(x[3], x[7]), t7 = csub(x[3], x[7]);
    t5 = cmul(t5, make_float2(C, -DIR * C));
    t6 = mulmi<DIR>(t6);
    t7 = cmul(t7, make_float2(-C, -DIR * C));
    float2 p0 = cadd(t0, t2), q0 = csub(t0, t2);
    float2 p1 = cadd(t1, t3), q1 = mulmi<DIR>(csub(t1, t3));
    x[0] = cadd(p0, p1); x[4] = csub(p0, p1);
    x[2] = cadd(q0, q1); x[6] = csub(q0, q1);
    float2 r0 = cadd(t4, t6), s0 = csub(t4, t6);
    float2 r1 = cadd(t5, t7), s1 = mulmi<DIR>(csub(t5, t7));
    x[1] = cadd(r0, r1); x[5] = csub(r0, r1);
    x[3] = cadd(s0, s1); x[7] = csub(s0, s1);
}

template<int DIR>
__device__ __forceinline__ void dft16(float2 x[16]) {
    float2 y[16];
#pragma unroll
    for (int b = 0; b < 4; b++) {
        float2 a0 = x[b], a1 = x[b + 4], a2 = x[b + 8], a3 = x[b + 12];
        float2 t0 = cadd(a0, a2), t1 = csub(a0, a2);
        float2 t2 = cadd(a1, a3), t3 = mulmi<DIR>(csub(a1, a3));
        y[b*4 + 0] = cadd(t0, t2);
        y[b*4 + 1] = cadd(t1, t3);
        y[b*4 + 2] = csub(t0, t2);
        y[b*4 + 3] = csub(t1, t3);
    }
    const float c1 = 0.9238795325112867f, s1 = 0.3826834323650898f;
    const float C = 0.70710678118654752f;
    const float2 w1 = make_float2(c1, -DIR * s1);
    const float2 w2 = make_float2(C, -DIR * C);
    const float2 w3 = make_float2(s1, -DIR * c1);
    const float2 w4 = make_float2(0.f, (float)(-DIR));
    const float2 w6 = make_float2(-C, -DIR * C);
    const float2 w9 = make_float2(-c1, DIR * s1);
    y[5]  = cmul(y[5],  w1); y[6]  = cmul(y[6],  w2); y[7]  = cmul(y[7],  w3);
    y[9]  = cmul(y[9],  w2); y[10] = cmul(y[10], w4); y[11] = cmul(y[11], w6);
    y[13] = cmul(y[13], w3); y[14] = cmul(y[14], w6); y[15] = cmul(y[15], w9);
#pragma unroll
    for (int k1 = 0; k1 < 4; k1++) {
        float2 a0 = y[k1], a1 = y[4 + k1], a2 = y[8 + k1], a3 = y[12 + k1];
        float2 t0 = cadd(a0, a2), t1 = csub(a0, a2);
        float2 t2 = cadd(a1, a3), t3 = mulmi<DIR>(csub(a1, a3));
        x[0*4 + k1] = cadd(t0, t2);
        x[1*4 + k1] = cadd(t1, t3);
        x[2*4 + k1] = csub(t0, t2);
        x[3*4 + k1] = csub(t1, t3);
    }
}

// FFT-512: 64-thread block, x[n1] = x[n1*64+t] entry, x[q2] = X[q2*64+t] exit.
template<int DIR>
__device__ __forceinline__ void fft512_core(float2 x[8], float2* s, int t) {
    dft8<DIR>(x);
    float2 w = g_tw[t];
    if (DIR < 0) w.y = -w.y;
    float2 cw = w;
#pragma unroll
    for (int k1 = 1; k1 < 8; k1++) { x[k1] = cmul(x[k1], cw); cw = cmul(cw, w); }
    {
        float4* s4 = reinterpret_cast<float4*>(s + (size_t)t * EX1S);
        s4[0] = make_float4(x[0].x, x[0].y, x[1].x, x[1].y);
        s4[1] = make_float4(x[2].x, x[2].y, x[3].x, x[3].y);
        s4[2] = make_float4(x[4].x, x[4].y, x[5].x, x[5].y);
        s4[3] = make_float4(x[6].x, x[6].y, x[7].x, x[7].y);
    }
    __syncthreads();
    int k1 = t >> 3, m2 = t & 7;
#pragma unroll
    for (int m1 = 0; m1 < 8; m1++) x[m1] = s[(m1 * 8 + m2) * EX1S + k1];
    __syncthreads();
    dft8<DIR>(x);
    w = g_tw[8 * m2];
    if (DIR < 0) w.y = -w.y;
    cw = w;
#pragma unroll
    for (int q1 = 1; q1 < 8; q1++) { x[q1] = cmul(x[q1], cw); cw = cmul(cw, w); }
#pragma unroll
    for (int q1 = 0; q1 < 8; q1++) s[m2 * P512B + q1 * 8 + k1] = x[q1];
    __syncthreads();
    int k1c = t & 7, q1c = t >> 3;
#pragma unroll
    for (int m = 0; m < 8; m++) x[m] = s[m * P512B + q1c * 8 + k1c];
    __syncthreads();
    dft8<DIR>(x);   // output: X[q2*64 + q1c*8 + k1c] = X[q2*64 + t]
}

// FFT-256: 16 threads/column (role q), column c. Entry x[n1]=x[n1*16+q],
// exit x[k2]=X[k2*16+q]. Exchange region is warp-private -> __syncwarp only.
template<int DIR>
__device__ __forceinline__ void fft256_core(float2 x[16], float2* E, int c, int q) {
    dft16<DIR>(x);
    float2 w = g_tw[2 * q];
    if (DIR < 0) w.y = -w.y;
    float2 cw = w;
#pragma unroll
    for (int k1 = 1; k1 < 16; k1++) { x[k1] = cmul(x[k1], cw); cw = cmul(cw, w); }
    {
        float4* e4 = reinterpret_cast<float4*>(E + c * E2C + q * E2S);
#pragma unroll
        for (int p = 0; p < 8; p++)
            e4[p] = make_float4(x[2*p].x, x[2*p].y, x[2*p+1].x, x[2*p+1].y);
    }
    __syncwarp();
#pragma unroll
    for (int n2 = 0; n2 < 16; n2++) x[n2] = E[c * E2C + n2 * E2S + q];
    __syncwarp();
    dft16<DIR>(x);
}

// Stage 1: one row per 64-thread block: pack z=u+ik, FFT-512, store fp16.
__global__ void __launch_bounds__(64) stage1_kernel(const float* __restrict__ u,
                                                    const float* __restrict__ kin) {
    __shared__ __align__(16) float2 sm[SROW];
    int t = threadIdx.x;
    int row = blockIdx.x;               // img*251 + h
    size_t ibase = (size_t)row * WW;
    float2 x[8];
#pragma unroll
    for (int a = 0; a < 8; a++) {
        int n = a * 64 + t;
        float ur = 0.f, kr = 0.f;
        if (n < WW) { ur = u[ibase + n]; kr = kin[ibase + n]; }
        x[a] = make_float2(ur, kr);
    }
    fft512_core<1>(x, sm, t);
    size_t obase = (size_t)row * ZP;
#pragma unroll
    for (int q2 = 0; q2 < 8; q2++)
        g_Zh[obase + q2 * 64 + t] = __float22half2_rn(x[q2]);
}

// Stage 2: per (image, 8-col tile), 128 threads (R8 math, smaller shape).
// Smem: E (18432) | T2h (8192) | Ms (9216) | Ps (9216) = 45056 B.
// c = t>>4 in [0,8): FFT column role; q = t&15: within-column role.
// Staging roles: qs = t&7 (staging col), cs = t>>3 (row sub-index).
__global__ void __launch_bounds__(128, 5) stage2_kernel() {
    extern __shared__ char dsmc[];
    float2*  E   = reinterpret_cast<float2*>(dsmc);            // 18432 B
    __half2* T2h = reinterpret_cast<__half2*>(dsmc + 18432);   //  8192 B
    __half2* Ms  = reinterpret_cast<__half2*>(dsmc + 26624);   //  9216 B
    __half2* Ps  = reinterpret_cast<__half2*>(dsmc + 35840);   //  9216 B
    const int t  = threadIdx.x;
    const int c  = t >> 4;
    const int q  = t & 15;
    const int qs = t & 7;
    const int cs = t >> 3;
    const int img = blockIdx.y;
    const int j0  = blockIdx.x * 8;
    const size_t zbase = (size_t)img * HH * ZP;
    const float CS   = 0.25f * 2.1073424255447017e-08f;  // 0.25 * 2^-25.5
    const float T2S  = CS * 4096.0f;                      // T2 pre-scale
    const float CS2  = CS * 64.0f;                        // product pre-scale
    const float T2D  = 1.0f / 64.0f;                      // 64/4096
    const __half2 hz = __float22half2_rn(make_float2(0.f, 0.f));
    float2 x[16];

    // ---- stage BOTH tiles (raw half2), loads issued back-to-back ----
    int jm = (512 - (j0 + qs)) & 511;
#pragma unroll
    for (int m = 0; m < 16; m++) {
        int h = cs + 16 * m;
        Ms[h * MST + qs] = (h < HH) ? g_Zh[zbase + (size_t)h * ZP + jm] : hz;
        Ps[h * MST + qs] = (h < HH) ? g_Zh[zbase + (size_t)h * ZP + j0 + qs] : hz;
    }
    __syncthreads();   // sync 1: staging complete

    // ---- mirror FFT (conj applied at transposed read) ----
#pragma unroll
    for (int n1 = 0; n1 < 16; n1++) {
        float2 v = __half22float2(Ms[(n1 * 16 + q) * MST + c]);
        x[n1] = make_float2(v.x, -v.y);
    }
    fft256_core<1>(x, E, c, q);          // x[k2] = Bbar

    // T2h = T2S * i * Bbar^2  (same thread writes & reads later)
#pragma unroll
    for (int k2 = 0; k2 < 16; k2++) {
        float2 pr = cmul(x[k2], x[k2]);
        T2h[c * 256 + k2 * 16 + q] =
            __float22half2_rn(make_float2(-T2S * pr.y, T2S * pr.x));
    }

    // ---- primary FFT (Ps stable since sync 1) ----
#pragma unroll
    for (int n1 = 0; n1 < 16; n1++)
        x[n1] = __half22float2(Ps[(n1 * 16 + q) * MST + c]);
    fft256_core<1>(x, E, c, q);          // x[k2] = A2

    // ---- product (x64 pre-scale for fp16 storage) ----
#pragma unroll
    for (int k2 = 0; k2 < 16; k2++) {
        float2 pr = cmul(x[k2], x[k2]);
        float2 t2 = __half22float2(T2h[c * 256 + k2 * 16 + q]);
        x[k2] = make_float2(CS2 * pr.y + t2.x * T2D,
                            -CS2 * pr.x + t2.y * T2D);
    }

    // ---- inverse column FFT ----
    fft256_core<-1>(x, E, c, q);

    // ---- out-stage into Ms: thread (c,q) writes exactly the cells it read
    //      (same column c, rows == q mod 16) -> no block sync needed before.
#pragma unroll
    for (int k2 = 0; k2 < 16; k2++)
        Ms[(k2 * 16 + q) * MST + c] = __float22half2_rn(x[k2]);
    __syncthreads();   // sync 2: out tile complete before cross-warp reads
    if (j0 + qs < NJ) {
        size_t pbase = (size_t)img * HH * WPAD + j0 + qs;
#pragma unroll
        for (int m = 0; m < 16; m++) {
            int h = cs + 16 * m;
            if (h < HH) g_Ph[pbase + (size_t)h * WPAD] = Ms[h * MST + qs];
        }
    }
}

// Stage 3: TWO rows per 64-thread block. x = P1ext + i*P2ext, one inverse
// FFT-512, y1 = Re -> row0, y2 = Im -> row1. Exact (linearity).
__global__ void __launch_bounds__(64) stage3_kernel(float* __restrict__ out) {
    __shared__ __align__(16) float2 sm[SROW];
    int t = threadIdx.x;
    int row0 = blockIdx.x * 2;
    size_t ib1 = (size_t)row0 * WPAD;
    size_t ib2 = ib1 + WPAD;
    float2 x[8];
#pragma unroll
    for (int a = 0; a < 8; a++) {
        int n = a * 64 + t;
        float2 p1, p2;
        if (n <= 256) {
            p1 = __half22float2(g_Ph[ib1 + n]);
            p2 = __half22float2(g_Ph[ib2 + n]);
        } else {
            float2 v1 = __half22float2(g_Ph[ib1 + 512 - n]);
            float2 v2 = __half22float2(g_Ph[ib2 + 512 - n]);
            p1 = make_float2(v1.x, -v1.y);
            p2 = make_float2(v2.x, -v2.y);
        }
        x[a] = make_float2(p1.x - p2.y, p1.y + p2.x);
    }
    fft512_core<-1>(x, sm, t);
    size_t ob1 = (size_t)row0 * WW;
    size_t ob2 = ob1 + WW;
    const float OD = 1.0f / 64.0f;
#pragma unroll
    for (int q2 = 0; q2 < 8; q2++) {
        int n = q2 * 64 + t;
        if (n < WW) {
            out[ob1 + n] = x[q2].x * OD;
            out[ob2 + n] = x[q2].y * OD;
        }
    }
}

extern "C" void kernel_launch(void* const* d_in, const int* in_sizes, int n_in,
                              void* d_out, int out_size) {
    const float* u  = (const float*)d_in[0];
    const float* kk = (const float*)d_in[1];
    float* out = (float*)d_out;

    cudaFuncSetAttribute(stage2_kernel,
                         cudaFuncAttributeMaxDynamicSharedMemorySize, 45056);

    init_tw_kernel<<<1, 512>>>();
    stage1_kernel<<<IMGS * HH, 64>>>(u, kk);         // 64256 rows
    stage2_kernel<<<dim3(33, IMGS), 128, 45056>>>(); // 33 x 8-col tiles x 256 imgs
    stage3_kernel<<<IMGS * HH / 2, 64>>>(out);       // 32128 row-pairs
}

// round 13
// speedup vs baseline: 1.0251x; 1.0251x over previous
#include <cuda_runtime.h>
#include <cuda_fp16.h>

// y = irfft2(rfft2(pad(u)) * rfft2(pad(k)), ortho) cropped.
// (4,64,251,509) fp32 -> 256 images 251x509, pad to 256x512.
// Pack z = u + i*k; with Z2 = FFT2(z):
//   P = U2*K2 = -0.25i*(Z2[ky,kx]^2 - conj(Z2[-ky,-kx])^2)
// conj(Z2[-ky,-kx]) = FFT_col(conj(Z[h,-kx])) -- conj-on-load, no gather.
// Combined ortho scale 2^-25.5 folded into the product.
// fp16 intermediates (tol 1e-3): g_Zh raw, g_Ph pre-scaled 2^6, T2 2^12.
// Stage2: in-place radix-4 dft16 (digit-reversed slots, compile-time renames)
// -> ~70 regs -> 3 blocks/SM at 70656B smem. Arithmetic identical to R8.
// Stage3 pairs two rows per inverse FFT-512 (y1 = Re, y2 = Im): exact.

#define IMGS 256
#define HH   251
#define WW   509
#define NJ   257
#define ZP   516   // half2 row stride of Z scratch
#define WPAD 260   // half2 row stride of product scratch
#define EX1S 10    // fft512 exchange-1 stride (16B aligned, conflict-free)
#define P512B 66   // fft512 exchange-2 stride (conflict-free both sides)
#define SROW 656   // smem float2 for fft512 (>= 64*10)
#define E2S  18    // fft256 exchange per-thread stride (float2)
#define E2C  288   // fft256 exchange per-column stride (float2) = 16*18
#define DR4(p) (((((p) & 3) << 2) | ((p) >> 2)))   // base-4 digit swap (involution)

__device__ __half2 g_Zh[IMGS * HH * ZP];   // packed row spectra (fp16)
__device__ __half2 g_Ph[IMGS * HH * WPAD]; // product half-spectrum (fp16, x64)
__device__ float2  g_tw[512];              // tw[r] = exp(-2*pi*i*r/512)

__global__ void init_tw_kernel() {
    int r = threadIdx.x;
    double ang = -2.0 * 3.141592653589793238462643383279502884 * (double)r / 512.0;
    g_tw[r] = make_float2((float)cos(ang), (float)sin(ang));
}

__device__ __forceinline__ float2 cmul(float2 a, float2 b) {
    return make_float2(a.x*b.x - a.y*b.y, a.x*b.y + a.y*b.x);
}
__device__ __forceinline__ float2 cadd(float2 a, float2 b) { return make_float2(a.x+b.x, a.y+b.y); }
__device__ __forceinline__ float2 csub(float2 a, float2 b) { return make_float2(a.x-b.x, a.y-b.y); }
template<int DIR>
__device__ __forceinline__ float2 mulmi(float2 v) {   // * (-i) fwd, * (+i) inv
    return (DIR == 1) ? make_float2(v.y, -v.x) : make_float2(-v.y, v.x);
}

template<int DIR>
__device__ __forceinline__ void dft8(float2 x[8]) {
    const float C = 0.70710678118654752f;
    float2 t0 = cadd(x[0], x[4]), t4 = csub(x[0], x[4]);
    float2 t1 = cadd(x[1], x[5]), t5 = csub(x[1], x[5]);
    float2 t2 = cadd(x[2], x[6]), t6 = csub(x[2], x[6]);
    float2 t3 = cadd(x[3], x[7]), t7 = csub(x[3], x[7]);
    t5 = cmul(t5, make_float2(C, -DIR * C));
    t6 = mulmi<DIR>(t6);
    t7 = cmul(t7, make_float2(-C, -DIR * C));
    float2 p0 = cadd(t0, t2), q0 = csub(t0, t2);
    float2 p1 = cadd(t1, t3), q1 = mulmi<DIR>(csub(t1, t3));
    x[0] = cadd(p0, p1); x[4] = csub(p0, p1);
    x[2] = cadd(q0, q1); x[6] = csub(q0, q1);
    float2 r0 = cadd(t4, t6), s0 = csub(t4, t6);
    float2 r1 = cadd(t5, t7), s1 = mulmi<DIR>(csub(t5, t7));
    x[1] = cadd(r0, r1); x[5] = csub(r0, r1);
    x[3] = cadd(s0, s1); x[7] = csub(s0, s1);
}

// In-place radix-4 DIF DFT-16 (same ops/twiddles as the radix-4x4 shadow
// version -> bit-identical results). Natural input in slots; on exit slot p
// holds X[DR4(p)]. All indices compile-time.
template<int DIR>
__device__ __forceinline__ void dif16ip(float2 x[16]) {
    const float c1 = 0.9238795325112867f, s1 = 0.3826834323650898f;
    const float C = 0.70710678118654752f;
    const float2 W1 = make_float2(c1, -DIR*s1);
    const float2 W2 = make_float2(C,  -DIR*C);
    const float2 W3 = make_float2(s1, -DIR*c1);
    const float2 W6 = make_float2(-C, -DIR*C);
    const float2 W9 = make_float2(-c1, DIR*s1);
#pragma unroll
    for (int n1 = 0; n1 < 4; n1++) {
        float2 a = x[n1], b = x[n1+4], c = x[n1+8], d = x[n1+12];
        float2 t0 = cadd(a,c), t1 = csub(a,c);
        float2 t2 = cadd(b,d), t3 = mulmi<DIR>(csub(b,d));
        float2 g0 = cadd(t0,t2), g1 = cadd(t1,t3);
        float2 g2 = csub(t0,t2), g3 = csub(t1,t3);
        if (n1 == 1)      { g1 = cmul(g1,W1); g2 = cmul(g2,W2); g3 = cmul(g3,W3); }
        else if (n1 == 2) { g1 = cmul(g1,W2); g2 = mulmi<DIR>(g2); g3 = cmul(g3,W6); }
        else if (n1 == 3) { g1 = cmul(g1,W3); g2 = cmul(g2,W6); g3 = cmul(g3,W9); }
        x[n1] = g0; x[n1+4] = g1; x[n1+8] = g2; x[n1+12] = g3;
    }
#pragma unroll
    for (int k2 = 0; k2 < 4; k2++) {
        float2 a = x[4*k2], b = x[4*k2+1], c = x[4*k2+2], d = x[4*k2+3];
        float2 t0 = cadd(a,c), t1 = csub(a,c);
        float2 t2 = cadd(b,d), t3 = mulmi<DIR>(csub(b,d));
        x[4*k2]   = cadd(t0,t2); x[4*k2+1] = cadd(t1,t3);
        x[4*k2+2] = csub(t0,t2); x[4*k2+3] = csub(t1,t3);
    }
}

// In-place radix-4 DIT DFT-16: entry slot p holds data[DR4(p)];
// natural-order output in slots. Same twiddle set.
template<int DIR>
__device__ __forceinline__ void dit16ip(float2 x[16]) {
    const float c1 = 0.9238795325112867f, s1 = 0.3826834323650898f;
    const float C = 0.70710678118654752f;
    const float2 W1 = make_float2(c1, -DIR*s1);
    const float2 W2 = make_float2(C,  -DIR*C);
    const float2 W3 = make_float2(s1, -DIR*c1);
    const float2 W6 = make_float2(-C, -DIR*C);
    const float2 W9 = make_float2(-c1, DIR*s1);
#pragma unroll
    for (int n0 = 0; n0 < 4; n0++) {
        float2 a = x[4*n0], b = x[4*n0+1], c = x[4*n0+2], d = x[4*n0+3];
        float2 t0 = cadd(a,c), t1 = csub(a,c);
        float2 t2 = cadd(b,d), t3 = mulmi<DIR>(csub(b,d));
        float2 g0 = cadd(t0,t2), g1 = cadd(t1,t3);
        float2 g2 = csub(t0,t2), g3 = csub(t1,t3);
        if (n0 == 1)      { g1 = cmul(g1,W1); g2 = cmul(g2,W2); g3 = cmul(g3,W3); }
        else if (n0 == 2) { g1 = cmul(g1,W2); g2 = mulmi<DIR>(g2); g3 = cmul(g3,W6); }
        else if (n0 == 3) { g1 = cmul(g1,W3); g2 = cmul(g2,W6); g3 = cmul(g3,W9); }
        x[4*n0] = g0; x[4*n0+1] = g1; x[4*n0+2] = g2; x[4*n0+3] = g3;
    }
#pragma unroll
    for (int k0 = 0; k0 < 4; k0++) {
        float2 a = x[k0], b = x[k0+4], c = x[k0+8], d = x[k0+12];
        float2 t0 = cadd(a,c), t1 = csub(a,c);
        float2 t2 = cadd(b,d), t3 = mulmi<DIR>(csub(b,d));
        x[k0]    = cadd(t0,t2); x[k0+4]  = cadd(t1,t3);
        x[k0+8]  = csub(t0,t2); x[k0+12] = csub(t1,t3);
    }
}

// FFT-512: 64-thread block, x[n1] = x[n1*64+t] entry, x[q2] = X[q2*64+t] exit.
template<int DIR>
__device__ __forceinline__ void fft512_core(float2 x[8], float2* s, int t) {
    dft8<DIR>(x);
    float2 w = g_tw[t];
    if (DIR < 0) w.y = -w.y;
    float2 cw = w;
#pragma unroll
    for (int k1 = 1; k1 < 8; k1++) { x[k1] = cmul(x[k1], cw); cw = cmul(cw, w); }
    {
        float4* s4 = reinterpret_cast<float4*>(s + (size_t)t * EX1S);
        s4[0] = make_float4(x[0].x, x[0].y, x[1].x, x[1].y);
        s4[1] = make_float4(x[2].x, x[2].y, x[3].x, x[3].y);
        s4[2] = make_float4(x[4].x, x[4].y, x[5].x, x[5].y);
        s4[3] = make_float4(x[6].x, x[6].y, x[7].x, x[7].y);
    }
    __syncthreads();
    int k1 = t >> 3, m2 = t & 7;
#pragma unroll
    for (int m1 = 0; m1 < 8; m1++) x[m1] = s[(m1 * 8 + m2) * EX1S + k1];
    __syncthreads();
    dft8<DIR>(x);
    w = g_tw[8 * m2];
    if (DIR < 0) w.y = -w.y;
    cw = w;
#pragma unroll
    for (int q1 = 1; q1 < 8; q1++) { x[q1] = cmul(x[q1], cw); cw = cmul(cw, w); }
#pragma unroll
    for (int q1 = 0; q1 < 8; q1++) s[m2 * P512B + q1 * 8 + k1] = x[q1];
    __syncthreads();
    int k1c = t & 7, q1c = t >> 3;
#pragma unroll
    for (int m = 0; m < 8; m++) x[m] = s[m * P512B + q1c * 8 + k1c];
    __syncthreads();
    dft8<DIR>(x);   // output: X[q2*64 + q1c*8 + k1c] = X[q2*64 + t]
}

// Forward FFT-256: entry x[n1] = col[n1*16+q] natural; exit slot p holds
// X[DR4(p)*16 + q]. Exchange identical to R8 (values at same positions).
template<int DIR>
__device__ __forceinline__ void fft256_fwd(float2 x[16], float2* E, int c, int q) {
    dif16ip<DIR>(x);                    // slot p = X1[DR4(p)]
    float2 w = g_tw[2 * q];
    if (DIR < 0) w.y = -w.y;
    float2 cw = make_float2(1.f, 0.f);
    {
        float4* e4 = reinterpret_cast<float4*>(E + c * E2C + q * E2S);
#pragma unroll
        for (int p = 0; p < 8; p++) {   // natural k1 = 2p, 2p+1
            float2 va = cmul(x[DR4(2*p)],   cw); cw = cmul(cw, w);
            float2 vb = cmul(x[DR4(2*p+1)], cw); cw = cmul(cw, w);
            e4[p] = make_float4(va.x, va.y, vb.x, vb.y);
        }
    }
    __syncwarp();
#pragma unroll
    for (int n2 = 0; n2 < 16; n2++) x[n2] = E[c * E2C + n2 * E2S + q];
    __syncwarp();
    dif16ip<DIR>(x);                    // slot p = X[DR4(p)*16 + q]
}

// Inverse FFT-256 consuming slot-order input: entry slot p = P[DR4(p)*16+q];
// exit slot p = z[DR4(p)*16 + q].
__device__ __forceinline__ void fft256_inv(float2 x[16], float2* E, int c, int q) {
    dit16ip<-1>(x);                     // natural r in slots
    float2 w = g_tw[2 * q];
    w.y = -w.y;
    float2 cw = make_float2(1.f, 0.f);
    {
        float4* e4 = reinterpret_cast<float4*>(E + c * E2C + q * E2S);
#pragma unroll
        for (int p = 0; p < 8; p++) {
            float2 va = cmul(x[2*p],   cw); cw = cmul(cw, w);
            float2 vb = cmul(x[2*p+1], cw); cw = cmul(cw, w);
            e4[p] = make_float4(va.x, va.y, vb.x, vb.y);
        }
    }
    __syncwarp();
#pragma unroll
    for (int n = 0; n < 16; n++) x[n] = E[c * E2C + n * E2S + q];
    __syncwarp();
    dif16ip<-1>(x);                     // slot p = z[DR4(p)*16 + q]
}

// Stage 1: one row per 64-thread block: pack z=u+ik, FFT-512, store fp16.
__global__ void __launch_bounds__(64) stage1_kernel(const float* __restrict__ u,
                                                    const float* __restrict__ kin) {
    __shared__ __align__(16) float2 sm[SROW];
    int t = threadIdx.x;
    int row = blockIdx.x;               // img*251 + h
    size_t ibase = (size_t)row * WW;
    float2 x[8];
#pragma unroll
    for (int a = 0; a < 8; a++) {
        int n = a * 64 + t;
        float ur = 0.f, kr = 0.f;
        if (n < WW) { ur = u[ibase + n]; kr = kin[ibase + n]; }
        x[a] = make_float2(ur, kr);
    }
    fft512_core<1>(x, sm, t);
    size_t obase = (size_t)row * ZP;
#pragma unroll
    for (int q2 = 0; q2 < 8; q2++)
        g_Zh[obase + q2 * 64 + t] = __float22half2_rn(x[q2]);
}

// Stage 2: per (image, 16-col tile), 256 threads, R8 arithmetic.
// Smem: E (36864, aliased with the Ms staging/out tile) | T2h (16384) |
// Ps (17408) = 70656 B -> 3 blocks/SM at <= 85 regs.
__global__ void __launch_bounds__(256, 3) stage2_kernel() {
    extern __shared__ char dsmc[];
    float2*  E   = reinterpret_cast<float2*>(dsmc);            // 36864 B
    __half2* Ms  = reinterpret_cast<__half2*>(dsmc);           // alias of E
    __half2* T2h = reinterpret_cast<__half2*>(dsmc + 36864);   // 16384 B
    __half2* Ps  = reinterpret_cast<__half2*>(dsmc + 53248);   // 17408 B
    const int t = threadIdx.x;
    const int c = t >> 4;
    const int q = t & 15;
    const int img = blockIdx.y;
    const int j0  = blockIdx.x * 16;
    const size_t zbase = (size_t)img * HH * ZP;
    const float CS   = 0.25f * 2.1073424255447017e-08f;  // 0.25 * 2^-25.5
    const float T2S  = CS * 4096.0f;                      // T2 pre-scale
    const float CS2  = CS * 64.0f;                        // product pre-scale
    const float T2D  = 1.0f / 64.0f;                      // 64/4096
    const __half2 hz = __float22half2_rn(make_float2(0.f, 0.f));
    float2 x[16];

    // ---- stage BOTH tiles (raw half2), loads issued back-to-back ----
    int jm = (512 - (j0 + q)) & 511;
#pragma unroll
    for (int m = 0; m < 16; m++) {
        int h = c + 16 * m;
        Ms[h * 17 + q] = (h < HH) ? g_Zh[zbase + (size_t)h * ZP + jm] : hz;
        Ps[h * 17 + q] = (h < HH) ? g_Zh[zbase + (size_t)h * ZP + j0 + q] : hz;
    }
    __syncthreads();   // sync 1: staging complete

    // ---- mirror transposed read (conj), then release Ms region to E ----
#pragma unroll
    for (int n1 = 0; n1 < 16; n1++) {
        float2 v = __half22float2(Ms[(n1 * 16 + q) * 17 + c]);
        x[n1] = make_float2(v.x, -v.y);
    }
    __syncthreads();   // sync 2: Ms reads done before E writes
    fft256_fwd<1>(x, E, c, q);          // slot p = Bbar[DR4(p)*16+q]

    // T2h (slot-aligned; same thread writes & reads later)
#pragma unroll
    for (int p = 0; p < 16; p++) {
        float2 pr = cmul(x[p], x[p]);
        T2h[c * 256 + p * 16 + q] =
            __float22half2_rn(make_float2(-T2S * pr.y, T2S * pr.x));
    }

    // ---- primary FFT (Ps dedicated, stable since sync 1) ----
#pragma unroll
    for (int n1 = 0; n1 < 16; n1++)
        x[n1] = __half22float2(Ps[(n1 * 16 + q) * 17 + c]);
    fft256_fwd<1>(x, E, c, q);          // slot p = A2[DR4(p)*16+q]

    // ---- product (slot-aligned; x64 pre-scale for fp16 storage) ----
#pragma unroll
    for (int p = 0; p < 16; p++) {
        float2 pr = cmul(x[p], x[p]);
        float2 t2 = __half22float2(T2h[c * 256 + p * 16 + q]);
        x[p] = make_float2(CS2 * pr.y + t2.x * T2D,
                           -CS2 * pr.x + t2.y * T2D);
    }

    // ---- inverse column FFT (slot input) ----
    fft256_inv(x, E, c, q);             // slot p = z[DR4(p)*16 + q]

    // ---- out-stage into Ms region (E fully consumed after sync 3) ----
    __syncthreads();   // sync 3
#pragma unroll
    for (int p = 0; p < 16; p++)
        Ms[(DR4(p) * 16 + q) * 17 + c] = __float22half2_rn(x[p]);
    __syncthreads();   // sync 4: out tile complete
    if (j0 + q < NJ) {
        size_t pbase = (size_t)img * HH * WPAD + j0 + q;
#pragma unroll
        for (int m = 0; m < 16; m++) {
            int h = c + 16 * m;
            if (h < HH) g_Ph[pbase + (size_t)h * WPAD] = Ms[h * 17 + q];
        }
    }
}

// Stage 3: TWO rows per 64-thread block. x = P1ext + i*P2ext, one inverse
// FFT-512, y1 = Re -> row0, y2 = Im -> row1. Exact (linearity).
__global__ void __launch_bounds__(64) stage3_kernel(float* __restrict__ out) {
    __shared__ __align__(16) float2 sm[SROW];
    int t = threadIdx.x;
    int row0 = blockIdx.x * 2;
    size_t ib1 = (size_t)row0 * WPAD;
    size_t ib2 = ib1 + WPAD;
    float2 x[8];
#pragma unroll
    for (int a = 0; a < 8; a++) {
        int n = a * 64 + t;
        float2 p1, p2;
        if (n <= 256) {
            p1 = __half22float2(g_Ph[ib1 + n]);
            p2 = __half22float2(g_Ph[ib2 + n]);
        } else {
            float2 v1 = __half22float2(g_Ph[ib1 + 512 - n]);
            float2 v2 = __half22float2(g_Ph[ib2 + 512 - n]);
            p1 = make_float2(v1.x, -v1.y);
            p2 = make_float2(v2.x, -v2.y);
        }
        x[a] = make_float2(p1.x - p2.y, p1.y + p2.x);
    }
    fft512_core<-1>(x, sm, t);
    size_t ob1 = (size_t)row0 * WW;
    size_t ob2 = ob1 + WW;
    const float OD = 1.0f / 64.0f;
#pragma unroll
    for (int q2 = 0; q2 < 8; q2++) {
        int n = q2 * 64 + t;
        if (n < WW) {
            out[ob1 + n] = x[q2].x * OD;
            out[ob2 + n] = x[q2].y * OD;
        }
    }
}

extern "C" void kernel_launch(void* const* d_in, const int* in_sizes, int n_in,
                              void* d_out, int out_size) {
    const float* u  = (const float*)d_in[0];
    const float* kk = (const float*)d_in[1];
    float* out = (float*)d_out;

    cudaFuncSetAttribute(stage2_kernel,
                         cudaFuncAttributeMaxDynamicSharedMemorySize, 70656);

    init_tw_kernel<<<1, 512>>>();
    stage1_kernel<<<IMGS * HH, 64>>>(u, kk);         // 64256 rows
    stage2_kernel<<<dim3(17, IMGS), 256, 70656>>>(); // 17 col-tiles x 256 images
    stage3_kernel<<<IMGS * HH / 2, 64>>>(out);       // 32128 row-pairs
}

// round 14
// speedup vs baseline: 1.0601x; 1.0342x over previous
#include <cuda_runtime.h>
#include <cuda_fp16.h>

// y = irfft2(rfft2(pad(u)) * rfft2(pad(k)), ortho) cropped.
// (4,64,251,509) fp32 -> 256 images 251x509, pad to 256x512.
// Pack z = u + i*k; with Z2 = FFT2(z):
//   P = U2*K2 = -0.25i*(Z2[ky,kx]^2 - conj(Z2[-ky,-kx])^2)
// conj(Z2[-ky,-kx]) = FFT_col(conj(Z[h,-kx])) -- conj-on-load, no gather.
// Combined ortho scale 2^-25.5 folded into the product.
// fp16 intermediates (tol 1e-3): g_Zh raw, g_Ph pre-scaled 2^6, T2 2^12.
// L2 residency: dead-after-read streams use __ldcs/__stcs; stage2 runs
// images in DESCENDING order (LIFO vs stage1's writes), which also makes
// stage3's natural ascending order LIFO vs stage2's writes.
// Stage3 pairs two rows per inverse FFT-512 (y1 = Re, y2 = Im): exact.

#define IMGS 256
#define HH   251
#define WW   509
#define NJ   257
#define ZP   516   // half2 row stride of Z scratch
#define WPAD 260   // half2 row stride of product scratch
#define EX1S 10    // fft512 exchange-1 stride (16B aligned, conflict-free)
#define P512B 66   // fft512 exchange-2 stride (conflict-free both sides)
#define SROW 656   // smem float2 for fft512 (>= 64*10)
#define E2S  18    // fft256 exchange per-thread stride (float2)
#define E2C  288   // fft256 exchange per-column stride (float2) = 16*18

__device__ __half2 g_Zh[IMGS * HH * ZP];   // packed row spectra (fp16)
__device__ __half2 g_Ph[IMGS * HH * WPAD]; // product half-spectrum (fp16, x64)
__device__ float2  g_tw[512];              // tw[r] = exp(-2*pi*i*r/512)

__global__ void init_tw_kernel() {
    int r = threadIdx.x;
    double ang = -2.0 * 3.141592653589793238462643383279502884 * (double)r / 512.0;
    g_tw[r] = make_float2((float)cos(ang), (float)sin(ang));
}

__device__ __forceinline__ float2 cmul(float2 a, float2 b) {
    return make_float2(a.x*b.x - a.y*b.y, a.x*b.y + a.y*b.x);
}
__device__ __forceinline__ float2 cadd(float2 a, float2 b) { return make_float2(a.x+b.x, a.y+b.y); }
__device__ __forceinline__ float2 csub(float2 a, float2 b) { return make_float2(a.x-b.x, a.y-b.y); }
template<int DIR>
__device__ __forceinline__ float2 mulmi(float2 v) {   // * (-i) fwd, * (+i) inv
    return (DIR == 1) ? make_float2(v.y, -v.x) : make_float2(-v.y, v.x);
}

template<int DIR>
__device__ __forceinline__ void dft8(float2 x[8]) {
    const float C = 0.70710678118654752f;
    float2 t0 = cadd(x[0], x[4]), t4 = csub(x[0], x[4]);
    float2 t1 = cadd(x[1], x[5]), t5 = csub(x[1], x[5]);
    float2 t2 = cadd(x[2], x[6]), t6 = csub(x[2], x[6]);
    float2 t3 = cadd(x[3], x[7]), t7 = csub(x[3], x[7]);
    t5 = cmul(t5, make_float2(C, -DIR * C));
    t6 = mulmi<DIR>(t6);
    t7 = cmul(t7, make_float2(-C, -DIR * C));
    float2 p0 = cadd(t0, t2), q0 = csub(t0, t2);
    float2 p1 = cadd(t1, t3), q1 = mulmi<DIR>(csub(t1, t3));
    x[0] = cadd(p0, p1); x[4] = csub(p0, p1);
    x[2] = cadd(q0, q1); x[6] = csub(q0, q1);
    float2 r0 = cadd(t4, t6), s0 = csub(t4, t6);
    float2 r1 = cadd(t5, t7), s1 = mulmi<DIR>(csub(t5, t7));
    x[1] = cadd(r0, r1); x[5] = csub(r0, r1);
    x[3] = cadd(s0, s1); x[7] = csub(s0, s1);
}

template<int DIR>
__device__ __forceinline__ void dft16(float2 x[16]) {
    float2 y[16];
#pragma unroll
    for (int b = 0; b < 4; b++) {
        float2 a0 = x[b], a1 = x[b + 4], a2 = x[b + 8], a3 = x[b + 12];
        float2 t0 = cadd(a0, a2), t1 = csub(a0, a2);
        float2 t2 = cadd(a1, a3), t3 = mulmi<DIR>(csub(a1, a3));
        y[b*4 + 0] = cadd(t0, t2);
        y[b*4 + 1] = cadd(t1, t3);
        y[b*4 + 2] = csub(t0, t2);
        y[b*4 + 3] = csub(t1, t3);
    }
    const float c1 = 0.9238795325112867f, s1 = 0.3826834323650898f;
    const float C = 0.70710678118654752f;
    const float2 w1 = make_float2(c1, -DIR * s1);
    const float2 w2 = make_float2(C, -DIR * C);
    const float2 w3 = make_float2(s1, -DIR * c1);
    const float2 w4 = make_float2(0.f, (float)(-DIR));
    const float2 w6 = make_float2(-C, -DIR * C);
    const float2 w9 = make_float2(-c1, DIR * s1);
    y[5]  = cmul(y[5],  w1); y[6]  = cmul(y[6],  w2); y[7]  = cmul(y[7],  w3);
    y[9]  = cmul(y[9],  w2); y[10] = cmul(y[10], w4); y[11] = cmul(y[11], w6);
    y[13] = cmul(y[13], w3); y[14] = cmul(y[14], w6); y[15] = cmul(y[15], w9);
#pragma unroll
    for (int k1 = 0; k1 < 4; k1++) {
        float2 a0 = y[k1], a1 = y[4 + k1], a2 = y[8 + k1], a3 = y[12 + k1];
        float2 t0 = cadd(a0, a2), t1 = csub(a0, a2);
        float2 t2 = cadd(a1, a3), t3 = mulmi<DIR>(csub(a1, a3));
        x[0*4 + k1] = cadd(t0, t2);
        x[1*4 + k1] = cadd(t1, t3);
        x[2*4 + k1] = csub(t0, t2);
        x[3*4 + k1] = csub(t1, t3);
    }
}

// FFT-512: 64-thread block, x[n1] = x[n1*64+t] entry, x[q2] = X[q2*64+t] exit.
template<int DIR>
__device__ __forceinline__ void fft512_core(float2 x[8], float2* s, int t) {
    dft8<DIR>(x);
    float2 w = g_tw[t];
    if (DIR < 0) w.y = -w.y;
    float2 cw = w;
#pragma unroll
    for (int k1 = 1; k1 < 8; k1++) { x[k1] = cmul(x[k1], cw); cw = cmul(cw, w); }
    {
        float4* s4 = reinterpret_cast<float4*>(s + (size_t)t * EX1S);
        s4[0] = make_float4(x[0].x, x[0].y, x[1].x, x[1].y);
        s4[1] = make_float4(x[2].x, x[2].y, x[3].x, x[3].y);
        s4[2] = make_float4(x[4].x, x[4].y, x[5].x, x[5].y);
        s4[3] = make_float4(x[6].x, x[6].y, x[7].x, x[7].y);
    }
    __syncthreads();
    int k1 = t >> 3, m2 = t & 7;
#pragma unroll
    for (int m1 = 0; m1 < 8; m1++) x[m1] = s[(m1 * 8 + m2) * EX1S + k1];
    __syncthreads();
    dft8<DIR>(x);
    w = g_tw[8 * m2];
    if (DIR < 0) w.y = -w.y;
    cw = w;
#pragma unroll
    for (int q1 = 1; q1 < 8; q1++) { x[q1] = cmul(x[q1], cw); cw = cmul(cw, w); }
#pragma unroll
    for (int q1 = 0; q1 < 8; q1++) s[m2 * P512B + q1 * 8 + k1] = x[q1];
    __syncthreads();
    int k1c = t & 7, q1c = t >> 3;
#pragma unroll
    for (int m = 0; m < 8; m++) x[m] = s[m * P512B + q1c * 8 + k1c];
    __syncthreads();
    dft8<DIR>(x);   // output: X[q2*64 + q1c*8 + k1c] = X[q2*64 + t]
}

// FFT-256: 16 threads/column (role q), column c. Entry x[n1]=x[n1*16+q],
// exit x[k2]=X[k2*16+q]. Exchange region is warp-private -> __syncwarp only.
template<int DIR>
__device__ __forceinline__ void fft256_core(float2 x[16], float2* E, int c, int q) {
    dft16<DIR>(x);
    float2 w = g_tw[2 * q];
    if (DIR < 0) w.y = -w.y;
    float2 cw = w;
#pragma unroll
    for (int k1 = 1; k1 < 16; k1++) { x[k1] = cmul(x[k1], cw); cw = cmul(cw, w); }
    {
        float4* e4 = reinterpret_cast<float4*>(E + c * E2C + q * E2S);
#pragma unroll
        for (int p = 0; p < 8; p++)
            e4[p] = make_float4(x[2*p].x, x[2*p].y, x[2*p+1].x, x[2*p+1].y);
    }
    __syncwarp();
#pragma unroll
    for (int n2 = 0; n2 < 16; n2++) x[n2] = E[c * E2C + n2 * E2S + q];
    __syncwarp();
    dft16<DIR>(x);
}

// Stage 1: one row per 64-thread block: pack z=u+ik, FFT-512, store fp16.
// Input reads are streamed (.cs): dead after this kernel, keep Z resident.
__global__ void __launch_bounds__(64) stage1_kernel(const float* __restrict__ u,
                                                    const float* __restrict__ kin) {
    __shared__ __align__(16) float2 sm[SROW];
    int t = threadIdx.x;
    int row = blockIdx.x;               // img*251 + h
    size_t ibase = (size_t)row * WW;
    float2 x[8];
#pragma unroll
    for (int a = 0; a < 8; a++) {
        int n = a * 64 + t;
        float ur = 0.f, kr = 0.f;
        if (n < WW) { ur = __ldcs(u + ibase + n); kr = __ldcs(kin + ibase + n); }
        x[a] = make_float2(ur, kr);
    }
    fft512_core<1>(x, sm, t);
    size_t obase = (size_t)row * ZP;
#pragma unroll
    for (int q2 = 0; q2 < 8; q2++)
        g_Zh[obase + q2 * 64 + t] = __float22half2_rn(x[q2]);
}

// Stage 2: per (image, 16-col tile). Images processed in DESCENDING order
// (LIFO vs stage1's Z writes -> L2 hits). Z reads streamed (.cs, dead after).
// Smem: E (18432x2=36864) | T2h (16384) | Ms (17408) | Ps (17408) = 88064 B.
__global__ void __launch_bounds__(256, 2) stage2_kernel() {
    extern __shared__ char dsmc[];
    float2*  E   = reinterpret_cast<float2*>(dsmc);            // 36864 B
    __half2* T2h = reinterpret_cast<__half2*>(dsmc + 36864);   // 16384 B
    __half2* Ms  = reinterpret_cast<__half2*>(dsmc + 53248);   // 17408 B
    __half2* Ps  = reinterpret_cast<__half2*>(dsmc + 70656);   // 17408 B
    const int t = threadIdx.x;
    const int c = t >> 4;
    const int q = t & 15;
    const int img = 255 - blockIdx.y;   // descending image order (L2 LIFO)
    const int j0  = blockIdx.x * 16;
    const size_t zbase = (size_t)img * HH * ZP;
    const float CS   = 0.25f * 2.1073424255447017e-08f;  // 0.25 * 2^-25.5
    const float T2S  = CS * 4096.0f;                      // T2 pre-scale
    const float CS2  = CS * 64.0f;                        // product pre-scale
    const float T2D  = 1.0f / 64.0f;                      // 64/4096
    const __half2 hz = __float22half2_rn(make_float2(0.f, 0.f));
    float2 x[16];

    // ---- stage BOTH tiles (raw half2, streamed), back-to-back loads ----
    int jm = (512 - (j0 + q)) & 511;
#pragma unroll
    for (int m = 0; m < 16; m++) {
        int h = c + 16 * m;
        Ms[h * 17 + q] = (h < HH) ? __ldcs(&g_Zh[zbase + (size_t)h * ZP + jm]) : hz;
        Ps[h * 17 + q] = (h < HH) ? __ldcs(&g_Zh[zbase + (size_t)h * ZP + j0 + q]) : hz;
    }
    __syncthreads();   // sync 1: staging complete

    // ---- mirror FFT (conj applied at transposed read) ----
#pragma unroll
    for (int n1 = 0; n1 < 16; n1++) {
        float2 v = __half22float2(Ms[(n1 * 16 + q) * 17 + c]);
        x[n1] = make_float2(v.x, -v.y);
    }
    fft256_core<1>(x, E, c, q);          // x[k2] = Bbar

    // T2h = T2S * i * Bbar^2  (same thread writes & reads later)
#pragma unroll
    for (int k2 = 0; k2 < 16; k2++) {
        float2 pr = cmul(x[k2], x[k2]);
        T2h[c * 256 + k2 * 16 + q] =
            __float22half2_rn(make_float2(-T2S * pr.y, T2S * pr.x));
    }

    // ---- primary FFT (Ps stable since sync 1) ----
#pragma unroll
    for (int n1 = 0; n1 < 16; n1++)
        x[n1] = __half22float2(Ps[(n1 * 16 + q) * 17 + c]);
    fft256_core<1>(x, E, c, q);          // x[k2] = A2

    // ---- product (x64 pre-scale for fp16 storage) ----
#pragma unroll
    for (int k2 = 0; k2 < 16; k2++) {
        float2 pr = cmul(x[k2], x[k2]);
        float2 t2 = __half22float2(T2h[c * 256 + k2 * 16 + q]);
        x[k2] = make_float2(CS2 * pr.y + t2.x * T2D,
                            -CS2 * pr.x + t2.y * T2D);
    }

    // ---- inverse column FFT ----
    fft256_core<-1>(x, E, c, q);

    // ---- stage out in half2 into Ms (all warps done reading Ms) ----
    __syncthreads();   // sync 2: lagging warps finish Ms transposed reads
#pragma unroll
    for (int k2 = 0; k2 < 16; k2++)
        Ms[(k2 * 16 + q) * 17 + c] = __float22half2_rn(x[k2]);
    __syncthreads();   // sync 3: out tile complete
    if (j0 + q < NJ) {
        size_t pbase = (size_t)img * HH * WPAD + j0 + q;
#pragma unroll
        for (int m = 0; m < 16; m++) {
            int h = c + 16 * m;
            if (h < HH) g_Ph[pbase + (size_t)h * WPAD] = Ms[h * 17 + q];
        }
    }
}

// Stage 3: TWO rows per 64-thread block. x = P1ext + i*P2ext, one inverse
// FFT-512, y1 = Re -> row0, y2 = Im -> row1. Exact (linearity).
// Natural ascending order is LIFO vs stage2's descending writes -> L2 hits.
// P reads streamed (.cs, dead after); output stores streamed (.cs).
__global__ void __launch_bounds__(64) stage3_kernel(float* __restrict__ out) {
    __shared__ __align__(16) float2 sm[SROW];
    int t = threadIdx.x;
    int row0 = blockIdx.x * 2;
    size_t ib1 = (size_t)row0 * WPAD;
    size_t ib2 = ib1 + WPAD;
    float2 x[8];
#pragma unroll
    for (int a = 0; a < 8; a++) {
        int n = a * 64 + t;
        float2 p1, p2;
        if (n <= 256) {
            p1 = __half22float2(__ldcs(&g_Ph[ib1 + n]));
            p2 = __half22float2(__ldcs(&g_Ph[ib2 + n]));
        } else {
            float2 v1 = __half22float2(__ldcs(&g_Ph[ib1 + 512 - n]));
            float2 v2 = __half22float2(__ldcs(&g_Ph[ib2 + 512 - n]));
            p1 = make_float2(v1.x, -v1.y);
            p2 = make_float2(v2.x, -v2.y);
        }
        x[a] = make_float2(p1.x - p2.y, p1.y + p2.x);
    }
    fft512_core<-1>(x, sm, t);
    size_t ob1 = (size_t)row0 * WW;
    size_t ob2 = ob1 + WW;
    const float OD = 1.0f / 64.0f;
#pragma unroll
    for (int q2 = 0; q2 < 8; q2++) {
        int n = q2 * 64 + t;
        if (n < WW) {
            __stcs(out + ob1 + n, x[q2].x * OD);
            __stcs(out + ob2 + n, x[q2].y * OD);
        }
    }
}

extern "C" void kernel_launch(void* const* d_in, const int* in_sizes, int n_in,
                              void* d_out, int out_size) {
    const float* u  = (const float*)d_in[0];
    const float* kk = (const float*)d_in[1];
    float* out = (float*)d_out;

    cudaFuncSetAttribute(stage2_kernel,
                         cudaFuncAttributeMaxDynamicSharedMemorySize, 88064);

    init_tw_kernel<<<1, 512>>>();
    stage1_kernel<<<IMGS * HH, 64>>>(u, kk);         // 64256 rows
    stage2_kernel<<<dim3(17, IMGS), 256, 88064>>>(); // 17 col-tiles x 256 images
    stage3_kernel<<<IMGS * HH / 2, 64>>>(out);       // 32128 row-pairs
}